// round 2
// baseline (speedup 1.0000x reference)
#include <cuda_runtime.h>
#include <math.h>

#define BN   32768      // B*N
#define NPTS 8192       // N
#define CH   64
#define KNB  32

typedef unsigned long long u64t;

// Scratch (device globals: no allocation allowed)
__device__ float g_P0[BN * CH];
__device__ float g_P1[BN * CH];
__device__ float g_Px2[BN * CH];
__device__ float g_P2[BN * CH];
__device__ float g_z[BN * CH];

__device__ __forceinline__ u64t pack2(float lo, float hi) {
    u64t r; asm("mov.b64 %0, {%1, %2};" : "=l"(r) : "f"(lo), "f"(hi)); return r;
}
__device__ __forceinline__ float2 unpack2(u64t v) {
    float2 r; asm("mov.b64 {%0, %1}, %2;" : "=f"(r.x), "=f"(r.y) : "l"(v)); return r;
}
// Packed fp32x2 FMA (sm_100+; PTX-only, ptxas never auto-fuses)
__device__ __forceinline__ void ffma2(u64t &d, u64t a, u64t b) {
    asm("fma.rn.f32x2 %0, %1, %2, %0;" : "+l"(d) : "l"(a), "l"(b));
}

// y (64 pre-duplicated pairs in smem) @ W(64x64 smem) -> pair for cols {2l, 2l+1}
__device__ __forceinline__ u64t mm64(const u64t* __restrict__ yb,
                                     const float* __restrict__ Wm,
                                     u64t acc, int l) {
    const u64t* Wu = (const u64t*)Wm;
#pragma unroll 8
    for (int c = 0; c < 64; c++) ffma2(acc, yb[c], Wu[c * 32 + l]);
    return acc;
}

__device__ __forceinline__ float lrelu(float v) { return fmaxf(v, 0.1f * v); }
__device__ __forceinline__ float sigmoidf_(float v) { return 1.0f / (1.0f + __expf(-v)); }

// ---------------------------------------------------------------------------
// Kernel 1: projections.  P0 = hx@W1[0][:128]+b1[0], P1 = hx@W1[1][:128]+b1[1],
//           Px2 = x@W1[2][64:128]+b1[2]
// ---------------------------------------------------------------------------
__global__ __launch_bounds__(512, 2) void k_proj(const float* __restrict__ h,
                                                 const float* __restrict__ x,
                                                 const float* __restrict__ W1,
                                                 const float* __restrict__ b1) {
    extern __shared__ float sm[];
    float* Wa0 = sm;              // 128*64
    float* Wa1 = sm + 8192;       // 128*64
    float* Wx2 = sm + 16384;      // 64*64
    float* hxs = sm + 20480;      // 16 warps * 128

    for (int i = threadIdx.x; i < 8192; i += 512) {
        Wa0[i] = W1[i];
        Wa1[i] = W1[131 * 64 + i];
    }
    for (int i = threadIdx.x; i < 4096; i += 512)
        Wx2[i] = W1[2 * 131 * 64 + 64 * 64 + i];
    __syncthreads();

    const int w = threadIdx.x >> 5, l = threadIdx.x & 31;
    const int d0 = 2 * l, d1 = 2 * l + 1;
    float* hxw = hxs + w * 128;
    const u64t* Wa0u = (const u64t*)Wa0;
    const u64t* Wa1u = (const u64t*)Wa1;
    const u64t* Wx2u = (const u64t*)Wx2;

    const u64t bb0 = pack2(b1[d0], b1[d1]);
    const u64t bb1 = pack2(b1[64 + d0], b1[64 + d1]);
    const u64t bb2 = pack2(b1[128 + d0], b1[128 + d1]);

    const int warpGlobal = blockIdx.x * 16 + w;
    const int stride = gridDim.x * 16;
    for (int p = warpGlobal; p < BN; p += stride) {
        float2 hv = ((const float2*)h)[p * 32 + l];
        float2 xv = ((const float2*)x)[p * 32 + l];
        __syncwarp();
        hxw[d0] = hv.x; hxw[d1] = hv.y;
        hxw[64 + d0] = xv.x; hxw[64 + d1] = xv.y;
        __syncwarp();

        u64t a0 = bb0, a1 = bb1, a2 = bb2;
#pragma unroll 4
        for (int c = 0; c < 64; c++) {
            float av = hxw[c], xc = hxw[64 + c];
            u64t ap = pack2(av, av), xp = pack2(xc, xc);
            ffma2(a0, ap, Wa0u[c * 32 + l]);
            ffma2(a1, ap, Wa1u[c * 32 + l]);
            ffma2(a0, xp, Wa0u[(64 + c) * 32 + l]);
            ffma2(a1, xp, Wa1u[(64 + c) * 32 + l]);
            ffma2(a2, xp, Wx2u[c * 32 + l]);
        }
        ((float2*)g_P0)[p * 32 + l] = unpack2(a0);
        ((float2*)g_P1)[p * 32 + l] = unpack2(a1);
        ((float2*)g_Px2)[p * 32 + l] = unpack2(a2);
    }
}

// ---------------------------------------------------------------------------
// Kernel 2: gather+pool for setconv0/1, tails -> z (stored), r -> rh -> P2
// ---------------------------------------------------------------------------
__global__ __launch_bounds__(512, 2) void k_zr(const float* __restrict__ h,
                                               const float* __restrict__ W1,
                                               const float* __restrict__ W2,
                                               const float* __restrict__ b2,
                                               const float* __restrict__ W3,
                                               const float* __restrict__ b3,
                                               const int* __restrict__ nidx,
                                               const float* __restrict__ ef) {
    extern __shared__ float sm[];
    float* W2_0 = sm;               // 4096
    float* W3_0 = sm + 4096;
    float* W2_1 = sm + 8192;
    float* W3_1 = sm + 12288;
    float* W1ch = sm + 16384;       // W1[2][0:64,:] (rh projection)
    float* Wb0 = sm + 20480;        // 3*64 edge rows, setconv0
    float* Wb1 = sm + 20672;        // setconv1
    float* b2_0 = sm + 20864; float* b3_0 = sm + 20928;
    float* b2_1 = sm + 20992; float* b3_1 = sm + 21056;
    // per-warp region: 256 floats = ybuf2(128) | idx(32) | edges(96)
    for (int i = threadIdx.x; i < 4096; i += 512) {
        W2_0[i] = W2[i];        W3_0[i] = W3[i];
        W2_1[i] = W2[4096 + i]; W3_1[i] = W3[4096 + i];
        W1ch[i] = W1[2 * 131 * 64 + i];
    }
    for (int i = threadIdx.x; i < 192; i += 512) {
        Wb0[i] = W1[128 * 64 + i];
        Wb1[i] = W1[131 * 64 + 128 * 64 + i];
    }
    if (threadIdx.x < 64) {
        b2_0[threadIdx.x] = b2[threadIdx.x];      b3_0[threadIdx.x] = b3[threadIdx.x];
        b2_1[threadIdx.x] = b2[64 + threadIdx.x]; b3_1[threadIdx.x] = b3[64 + threadIdx.x];
    }
    __syncthreads();

    const int w = threadIdx.x >> 5, l = threadIdx.x & 31;
    const int d0 = 2 * l, d1 = 2 * l + 1;
    float* wb = sm + 21120 + w * 256;
    u64t* yb = (u64t*)wb;
    int* idxw = (int*)(wb + 128);
    float* ew = wb + 160;

    // hoist the 12 edge-weight scalars this lane needs
    const float e00 = Wb0[d0], e01 = Wb0[64 + d0], e02 = Wb0[128 + d0];
    const float e03 = Wb0[d1], e04 = Wb0[64 + d1], e05 = Wb0[128 + d1];
    const float e10 = Wb1[d0], e11 = Wb1[64 + d0], e12 = Wb1[128 + d0];
    const float e13 = Wb1[d1], e14 = Wb1[64 + d1], e15 = Wb1[128 + d1];
    const u64t bias20 = pack2(b2_0[d0], b2_0[d1]), bias30 = pack2(b3_0[d0], b3_0[d1]);
    const u64t bias21 = pack2(b2_1[d0], b2_1[d1]), bias31 = pack2(b3_1[d0], b3_1[d1]);

    const int warpGlobal = blockIdx.x * 16 + w;
    const int stride = gridDim.x * 16;
    for (int p = warpGlobal; p < BN; p += stride) {
        __syncwarp();
        idxw[l] = nidx[p * 32 + l];
        ew[l] = ef[p * 96 + l];
        ew[32 + l] = ef[p * 96 + 32 + l];
        ew[64 + l] = ef[p * 96 + 64 + l];
        __syncwarp();

        const int rowbase = p & ~(NPTS - 1);     // b*N
        const float* P0b = g_P0 + (size_t)rowbase * 64 + d0;
        const float* P1b = g_P1 + (size_t)rowbase * 64 + d0;
        float m0a = -3e38f, m0b = -3e38f, m1a = -3e38f, m1b = -3e38f;
#pragma unroll 4
        for (int k = 0; k < KNB; k++) {
            const int joff = idxw[k] * 64;
            float2 q0 = *(const float2*)(P0b + joff);
            float2 q1 = *(const float2*)(P1b + joff);
            float f0 = ew[3 * k], f1 = ew[3 * k + 1], f2 = ew[3 * k + 2];
            float t;
            t = fmaf(f0, e00, fmaf(f1, e01, f2 * e02)); m0a = fmaxf(m0a, q0.x + t);
            t = fmaf(f0, e03, fmaf(f1, e04, f2 * e05)); m0b = fmaxf(m0b, q0.y + t);
            t = fmaf(f0, e10, fmaf(f1, e11, f2 * e12)); m1a = fmaxf(m1a, q1.x + t);
            t = fmaf(f0, e13, fmaf(f1, e14, f2 * e15)); m1b = fmaxf(m1b, q1.y + t);
        }

        // --- setconv 0 tail -> z ---
        float ya = lrelu(m0a), yc = lrelu(m0b);
        __syncwarp();
        yb[d0] = pack2(ya, ya); yb[d1] = pack2(yc, yc);
        __syncwarp();
        float2 t0 = unpack2(mm64(yb, W2_0, bias20, l));
        t0.x = lrelu(t0.x); t0.y = lrelu(t0.y);
        __syncwarp();
        yb[d0] = pack2(t0.x, t0.x); yb[d1] = pack2(t0.y, t0.y);
        __syncwarp();
        float2 zf = unpack2(mm64(yb, W3_0, bias30, l));
        zf.x = sigmoidf_(zf.x); zf.y = sigmoidf_(zf.y);
        ((float2*)g_z)[p * 32 + l] = zf;

        // --- setconv 1 tail -> r -> rh -> P2 ---
        ya = lrelu(m1a); yc = lrelu(m1b);
        __syncwarp();
        yb[d0] = pack2(ya, ya); yb[d1] = pack2(yc, yc);
        __syncwarp();
        float2 t1 = unpack2(mm64(yb, W2_1, bias21, l));
        t1.x = lrelu(t1.x); t1.y = lrelu(t1.y);
        __syncwarp();
        yb[d0] = pack2(t1.x, t1.x); yb[d1] = pack2(t1.y, t1.y);
        __syncwarp();
        float2 rf = unpack2(mm64(yb, W3_1, bias31, l));
        rf.x = sigmoidf_(rf.x); rf.y = sigmoidf_(rf.y);

        float2 hv = ((const float2*)h)[p * 32 + l];
        float rha = rf.x * hv.x, rhb = rf.y * hv.y;
        __syncwarp();
        yb[d0] = pack2(rha, rha); yb[d1] = pack2(rhb, rhb);
        __syncwarp();
        float2 px = ((const float2*)g_Px2)[p * 32 + l];
        float2 p2 = unpack2(mm64(yb, W1ch, pack2(px.x, px.y), l));
        ((float2*)g_P2)[p * 32 + l] = p2;
    }
}

// ---------------------------------------------------------------------------
// Kernel 3: gather+pool for setconv2, tail -> q, out = h + z*(q-h)
// ---------------------------------------------------------------------------
__global__ __launch_bounds__(512, 2) void k_out(const float* __restrict__ h,
                                                const float* __restrict__ W1,
                                                const float* __restrict__ W2,
                                                const float* __restrict__ b2,
                                                const float* __restrict__ W3,
                                                const float* __restrict__ b3,
                                                const int* __restrict__ nidx,
                                                const float* __restrict__ ef,
                                                float* __restrict__ out) {
    extern __shared__ float sm[];
    float* W2_2 = sm;               // 4096
    float* W3_2 = sm + 4096;        // 4096
    float* Wb2 = sm + 8192;         // 192
    float* b2_2 = sm + 8384;
    float* b3_2 = sm + 8448;
    // per-warp region at 8512: 256 floats each

    for (int i = threadIdx.x; i < 4096; i += 512) {
        W2_2[i] = W2[2 * 4096 + i];
        W3_2[i] = W3[2 * 4096 + i];
    }
    for (int i = threadIdx.x; i < 192; i += 512)
        Wb2[i] = W1[2 * 131 * 64 + 128 * 64 + i];
    if (threadIdx.x < 64) {
        b2_2[threadIdx.x] = b2[128 + threadIdx.x];
        b3_2[threadIdx.x] = b3[128 + threadIdx.x];
    }
    __syncthreads();

    const int w = threadIdx.x >> 5, l = threadIdx.x & 31;
    const int d0 = 2 * l, d1 = 2 * l + 1;
    float* wb = sm + 8512 + w * 256;
    u64t* yb = (u64t*)wb;
    int* idxw = (int*)(wb + 128);
    float* ew = wb + 160;

    const float e20 = Wb2[d0], e21 = Wb2[64 + d0], e22 = Wb2[128 + d0];
    const float e23 = Wb2[d1], e24 = Wb2[64 + d1], e25 = Wb2[128 + d1];
    const u64t bias2 = pack2(b2_2[d0], b2_2[d1]), bias3 = pack2(b3_2[d0], b3_2[d1]);

    const int warpGlobal = blockIdx.x * 16 + w;
    const int stride = gridDim.x * 16;
    for (int p = warpGlobal; p < BN; p += stride) {
        __syncwarp();
        idxw[l] = nidx[p * 32 + l];
        ew[l] = ef[p * 96 + l];
        ew[32 + l] = ef[p * 96 + 32 + l];
        ew[64 + l] = ef[p * 96 + 64 + l];
        __syncwarp();

        const int rowbase = p & ~(NPTS - 1);
        const float* P2b = g_P2 + (size_t)rowbase * 64 + d0;
        float ma = -3e38f, mb = -3e38f;
#pragma unroll 4
        for (int k = 0; k < KNB; k++) {
            const int joff = idxw[k] * 64;
            float2 q = *(const float2*)(P2b + joff);
            float f0 = ew[3 * k], f1 = ew[3 * k + 1], f2 = ew[3 * k + 2];
            float t;
            t = fmaf(f0, e20, fmaf(f1, e21, f2 * e22)); ma = fmaxf(ma, q.x + t);
            t = fmaf(f0, e23, fmaf(f1, e24, f2 * e25)); mb = fmaxf(mb, q.y + t);
        }
        float ya = lrelu(ma), yc = lrelu(mb);
        __syncwarp();
        yb[d0] = pack2(ya, ya); yb[d1] = pack2(yc, yc);
        __syncwarp();
        float2 t0 = unpack2(mm64(yb, W2_2, bias2, l));
        t0.x = lrelu(t0.x); t0.y = lrelu(t0.y);
        __syncwarp();
        yb[d0] = pack2(t0.x, t0.x); yb[d1] = pack2(t0.y, t0.y);
        __syncwarp();
        float2 qf = unpack2(mm64(yb, W3_2, bias3, l));
        qf.x = tanhf(qf.x); qf.y = tanhf(qf.y);

        float2 zf = ((const float2*)g_z)[p * 32 + l];
        float2 hv = ((const float2*)h)[p * 32 + l];
        float2 o;
        o.x = hv.x + zf.x * (qf.x - hv.x);
        o.y = hv.y + zf.y * (qf.y - hv.y);
        ((float2*)out)[p * 32 + l] = o;
    }
}

// ---------------------------------------------------------------------------
extern "C" void kernel_launch(void* const* d_in, const int* in_sizes, int n_in,
                              void* d_out, int out_size) {
    const float* h  = (const float*)d_in[0];
    const float* x  = (const float*)d_in[1];
    // d_in[2] = c (unused by reference)
    const float* W1 = (const float*)d_in[3];
    const float* b1 = (const float*)d_in[4];
    const float* W2 = (const float*)d_in[5];
    const float* b2 = (const float*)d_in[6];
    const float* W3 = (const float*)d_in[7];
    const float* b3 = (const float*)d_in[8];
    const int* nidx = (const int*)d_in[9];
    const float* ef = (const float*)d_in[10];
    float* out = (float*)d_out;

    const int SMEM1 = 22528 * 4;   // 90112 B
    const int SMEM2 = 25216 * 4;   // 100864 B
    const int SMEM3 = 12608 * 4;   // 50432 B
    cudaFuncSetAttribute(k_proj, cudaFuncAttributeMaxDynamicSharedMemorySize, SMEM1);
    cudaFuncSetAttribute(k_zr,   cudaFuncAttributeMaxDynamicSharedMemorySize, SMEM2);
    cudaFuncSetAttribute(k_out,  cudaFuncAttributeMaxDynamicSharedMemorySize, SMEM3);

    const int GRID = 304;  // 2 blocks/SM on 152 SMs
    k_proj<<<GRID, 512, SMEM1>>>(h, x, W1, b1);
    k_zr  <<<GRID, 512, SMEM2>>>(h, W1, W2, b2, W3, b3, nidx, ef);
    k_out <<<GRID, 512, SMEM3>>>(h, W1, W2, b2, W3, b3, nidx, ef, out);
}

// round 3
// speedup vs baseline: 1.3146x; 1.3146x over previous
#include <cuda_runtime.h>
#include <math.h>

#define BN   32768      // B*N
#define NPTS 8192       // N
#define KNB  32

typedef unsigned long long u64t;

// Scratch (device globals: no allocation allowed)
__device__ float g_P0[BN * 64];
__device__ float g_P1[BN * 64];
__device__ float g_Px2[BN * 64];
__device__ float g_P2[BN * 64];
__device__ float g_z[BN * 64];

__device__ __forceinline__ u64t pack2(float lo, float hi) {
    u64t r; asm("mov.b64 %0, {%1, %2};" : "=l"(r) : "f"(lo), "f"(hi)); return r;
}
__device__ __forceinline__ float2 unpack2(u64t v) {
    float2 r; asm("mov.b64 {%0, %1}, %2;" : "=f"(r.x), "=f"(r.y) : "l"(v)); return r;
}
// Packed fp32x2 FMA (sm_100+; PTX-only, ptxas never auto-fuses)
__device__ __forceinline__ void ffma2(u64t &d, u64t a, u64t b) {
    asm("fma.rn.f32x2 %0, %1, %2, %0;" : "+l"(d) : "l"(a), "l"(b));
}

__device__ __forceinline__ float lrelu(float v) { return fmaxf(v, 0.1f * v); }
__device__ __forceinline__ float sigmoidf_(float v) { return 1.0f / (1.0f + __expf(-v)); }

// Batched 64x64 matmul tail: 4 points' pre-duplicated activations (yb, 4x64 u64
// pairs) times W (64x64 smem). Weight pair loaded ONCE per channel, applied to
// all 4 points (register blocking -> 4x less smem crossbar traffic).
__device__ __forceinline__ void mm64b(const u64t* __restrict__ yb,
                                      const float* __restrict__ Wm,
                                      u64t* acc, int l) {
    const u64t* Wu = (const u64t*)Wm;
#pragma unroll 8
    for (int c = 0; c < 64; c++) {
        u64t wv = Wu[c * 32 + l];
        ffma2(acc[0], yb[c],       wv);
        ffma2(acc[1], yb[64 + c],  wv);
        ffma2(acc[2], yb[128 + c], wv);
        ffma2(acc[3], yb[192 + c], wv);
    }
}

// ---------------------------------------------------------------------------
// Kernel 1: projections (T=4 points per warp pass).
//   P0 = hx@W1[0][:128]+b1[0], P1 = hx@W1[1][:128]+b1[1], Px2 = x@W1[2][64:128]+b1[2]
// ---------------------------------------------------------------------------
__global__ __launch_bounds__(512, 1) void k_proj(const float* __restrict__ h,
                                                 const float* __restrict__ x,
                                                 const float* __restrict__ W1,
                                                 const float* __restrict__ b1) {
    extern __shared__ float sm[];
    float* Wa0 = sm;              // 128*64
    float* Wa1 = sm + 8192;       // 128*64
    float* Wx2 = sm + 16384;      // 64*64
    // per-warp duplicated activations: 4 pts * 128 ch * u64 = 1024 floats

    for (int i = threadIdx.x; i < 8192; i += 512) {
        Wa0[i] = W1[i];
        Wa1[i] = W1[8384 + i];            // 131*64
    }
    for (int i = threadIdx.x; i < 4096; i += 512)
        Wx2[i] = W1[20864 + i];           // 2*131*64 + 64*64
    __syncthreads();

    const int w = threadIdx.x >> 5, l = threadIdx.x & 31;
    const int d0 = 2 * l, d1 = d0 + 1;
    u64t* actd = (u64t*)(sm + 20480 + w * 1024);
    const u64t* Wa0u = (const u64t*)Wa0;
    const u64t* Wa1u = (const u64t*)Wa1;
    const u64t* Wx2u = (const u64t*)Wx2;

    const u64t bb0 = pack2(b1[d0], b1[d1]);
    const u64t bb1 = pack2(b1[64 + d0], b1[64 + d1]);
    const u64t bb2 = pack2(b1[128 + d0], b1[128 + d1]);

    const int stride = gridDim.x * 16;
    for (int g = blockIdx.x * 16 + w; g < BN / 4; g += stride) {
        const int base = g * 4;
        __syncwarp();
#pragma unroll
        for (int t = 0; t < 4; t++) {
            float2 hv = ((const float2*)h)[(size_t)(base + t) * 32 + l];
            float2 xv = ((const float2*)x)[(size_t)(base + t) * 32 + l];
            actd[t * 128 + d0] = pack2(hv.x, hv.x);
            actd[t * 128 + d1] = pack2(hv.y, hv.y);
            actd[t * 128 + 64 + d0] = pack2(xv.x, xv.x);
            actd[t * 128 + 64 + d1] = pack2(xv.y, xv.y);
        }
        __syncwarp();

        u64t a0[4] = {bb0, bb0, bb0, bb0};
        u64t a1[4] = {bb1, bb1, bb1, bb1};
        u64t a2[4] = {bb2, bb2, bb2, bb2};
#pragma unroll 4
        for (int c = 0; c < 64; c++) {
            u64t wh0 = Wa0u[c * 32 + l], wx0 = Wa0u[(64 + c) * 32 + l];
            u64t wh1 = Wa1u[c * 32 + l], wx1 = Wa1u[(64 + c) * 32 + l];
            u64t wxx = Wx2u[c * 32 + l];
#pragma unroll
            for (int t = 0; t < 4; t++) {
                u64t av = actd[t * 128 + c];
                u64t xvv = actd[t * 128 + 64 + c];
                ffma2(a0[t], av, wh0);
                ffma2(a0[t], xvv, wx0);
                ffma2(a1[t], av, wh1);
                ffma2(a1[t], xvv, wx1);
                ffma2(a2[t], xvv, wxx);
            }
        }
#pragma unroll
        for (int t = 0; t < 4; t++) {
            ((float2*)g_P0)[(size_t)(base + t) * 32 + l] = unpack2(a0[t]);
            ((float2*)g_P1)[(size_t)(base + t) * 32 + l] = unpack2(a1[t]);
            ((float2*)g_Px2)[(size_t)(base + t) * 32 + l] = unpack2(a2[t]);
        }
    }
}

// ---------------------------------------------------------------------------
// Kernel 2: gather+pool for setconv0/1 (T=4), tails -> z (stored), r -> rh -> P2
// ---------------------------------------------------------------------------
__global__ __launch_bounds__(512, 1) void k_zr(const float* __restrict__ h,
                                               const float* __restrict__ W1,
                                               const float* __restrict__ W2,
                                               const float* __restrict__ b2,
                                               const float* __restrict__ W3,
                                               const float* __restrict__ b3,
                                               const int* __restrict__ nidx,
                                               const float* __restrict__ ef) {
    extern __shared__ float sm[];
    float* W2_0 = sm;               // 4096 each
    float* W3_0 = sm + 4096;
    float* W2_1 = sm + 8192;
    float* W3_1 = sm + 12288;
    float* W1ch = sm + 16384;       // W1[2][0:64,:]
    // per-warp region 1024 floats: yb(512) | idx(128) | ef(384)

    for (int i = threadIdx.x; i < 4096; i += 512) {
        W2_0[i] = W2[i];        W3_0[i] = W3[i];
        W2_1[i] = W2[4096 + i]; W3_1[i] = W3[4096 + i];
        W1ch[i] = W1[16768 + i];
    }
    __syncthreads();

    const int w = threadIdx.x >> 5, l = threadIdx.x & 31;
    const int d0 = 2 * l, d1 = d0 + 1;
    float* wb = sm + 20480 + w * 1024;
    u64t* yb = (u64t*)wb;            // 256 u64
    int* idxw = (int*)(wb + 512);    // 128 ints
    float* ew = wb + 640;            // 384 floats

    const float* Wb0 = W1 + 128 * 64;
    const float* Wb1 = W1 + 8384 + 128 * 64;
    const float e00 = Wb0[d0], e01 = Wb0[64 + d0], e02 = Wb0[128 + d0];
    const float e03 = Wb0[d1], e04 = Wb0[64 + d1], e05 = Wb0[128 + d1];
    const float e10 = Wb1[d0], e11 = Wb1[64 + d0], e12 = Wb1[128 + d0];
    const float e13 = Wb1[d1], e14 = Wb1[64 + d1], e15 = Wb1[128 + d1];
    const u64t bias20 = pack2(b2[d0], b2[d1]), bias30 = pack2(b3[d0], b3[d1]);
    const u64t bias21 = pack2(b2[64 + d0], b2[64 + d1]), bias31 = pack2(b3[64 + d0], b3[64 + d1]);

    const int stride = gridDim.x * 16;
    for (int g = blockIdx.x * 16 + w; g < BN / 4; g += stride) {
        const int base = g * 4;
        __syncwarp();
#pragma unroll
        for (int t = 0; t < 4; t++)
            idxw[t * 32 + l] = nidx[(size_t)(base + t) * 32 + l];
#pragma unroll
        for (int i = 0; i < 12; i++)
            ew[i * 32 + l] = ef[(size_t)base * 96 + i * 32 + l];
        __syncwarp();

        const size_t rowbase = (size_t)(base & ~(NPTS - 1)) * 64;
        const float* P0b = g_P0 + rowbase + d0;
        const float* P1b = g_P1 + rowbase + d0;
        float m0a[4], m0b[4], m1a[4], m1b[4];
#pragma unroll
        for (int t = 0; t < 4; t++) { m0a[t] = m0b[t] = m1a[t] = m1b[t] = -3e38f; }
#pragma unroll
        for (int t = 0; t < 4; t++) {
#pragma unroll 8
            for (int k = 0; k < KNB; k++) {
                const int joff = idxw[t * 32 + k] * 64;
                float2 q0 = *(const float2*)(P0b + joff);
                float2 q1 = *(const float2*)(P1b + joff);
                float f0 = ew[t * 96 + 3 * k], f1 = ew[t * 96 + 3 * k + 1], f2 = ew[t * 96 + 3 * k + 2];
                float tt;
                tt = fmaf(f0, e00, fmaf(f1, e01, f2 * e02)); m0a[t] = fmaxf(m0a[t], q0.x + tt);
                tt = fmaf(f0, e03, fmaf(f1, e04, f2 * e05)); m0b[t] = fmaxf(m0b[t], q0.y + tt);
                tt = fmaf(f0, e10, fmaf(f1, e11, f2 * e12)); m1a[t] = fmaxf(m1a[t], q1.x + tt);
                tt = fmaf(f0, e13, fmaf(f1, e14, f2 * e15)); m1b[t] = fmaxf(m1b[t], q1.y + tt);
            }
        }

        // --- setconv 0 tail -> z ---
        __syncwarp();
#pragma unroll
        for (int t = 0; t < 4; t++) {
            float ya = lrelu(m0a[t]), yc = lrelu(m0b[t]);
            yb[t * 64 + d0] = pack2(ya, ya);
            yb[t * 64 + d1] = pack2(yc, yc);
        }
        __syncwarp();
        u64t acc[4] = {bias20, bias20, bias20, bias20};
        mm64b(yb, W2_0, acc, l);
        __syncwarp();
#pragma unroll
        for (int t = 0; t < 4; t++) {
            float2 v = unpack2(acc[t]);
            v.x = lrelu(v.x); v.y = lrelu(v.y);
            yb[t * 64 + d0] = pack2(v.x, v.x);
            yb[t * 64 + d1] = pack2(v.y, v.y);
        }
        __syncwarp();
        acc[0] = acc[1] = acc[2] = acc[3] = bias30;
        mm64b(yb, W3_0, acc, l);
#pragma unroll
        for (int t = 0; t < 4; t++) {
            float2 v = unpack2(acc[t]);
            float2 zf; zf.x = sigmoidf_(v.x); zf.y = sigmoidf_(v.y);
            ((float2*)g_z)[(size_t)(base + t) * 32 + l] = zf;
        }

        // --- setconv 1 tail -> r -> rh -> P2 ---
        __syncwarp();
#pragma unroll
        for (int t = 0; t < 4; t++) {
            float ya = lrelu(m1a[t]), yc = lrelu(m1b[t]);
            yb[t * 64 + d0] = pack2(ya, ya);
            yb[t * 64 + d1] = pack2(yc, yc);
        }
        __syncwarp();
        acc[0] = acc[1] = acc[2] = acc[3] = bias21;
        mm64b(yb, W2_1, acc, l);
        __syncwarp();
#pragma unroll
        for (int t = 0; t < 4; t++) {
            float2 v = unpack2(acc[t]);
            v.x = lrelu(v.x); v.y = lrelu(v.y);
            yb[t * 64 + d0] = pack2(v.x, v.x);
            yb[t * 64 + d1] = pack2(v.y, v.y);
        }
        __syncwarp();
        acc[0] = acc[1] = acc[2] = acc[3] = bias31;
        mm64b(yb, W3_1, acc, l);
        __syncwarp();
#pragma unroll
        for (int t = 0; t < 4; t++) {
            float2 v = unpack2(acc[t]);
            float2 hv = ((const float2*)h)[(size_t)(base + t) * 32 + l];
            float ra = sigmoidf_(v.x) * hv.x;
            float rb = sigmoidf_(v.y) * hv.y;
            yb[t * 64 + d0] = pack2(ra, ra);
            yb[t * 64 + d1] = pack2(rb, rb);
        }
        __syncwarp();
        {
            u64t a[4];
#pragma unroll
            for (int t = 0; t < 4; t++) {
                float2 px = ((const float2*)g_Px2)[(size_t)(base + t) * 32 + l];
                a[t] = pack2(px.x, px.y);
            }
            mm64b(yb, W1ch, a, l);
#pragma unroll
            for (int t = 0; t < 4; t++)
                ((float2*)g_P2)[(size_t)(base + t) * 32 + l] = unpack2(a[t]);
        }
    }
}

// ---------------------------------------------------------------------------
// Kernel 3: gather+pool for setconv2 (T=4), tail -> q, out = h + z*(q-h)
// ---------------------------------------------------------------------------
__global__ __launch_bounds__(512, 2) void k_out(const float* __restrict__ h,
                                                const float* __restrict__ W1,
                                                const float* __restrict__ W2,
                                                const float* __restrict__ b2,
                                                const float* __restrict__ W3,
                                                const float* __restrict__ b3,
                                                const int* __restrict__ nidx,
                                                const float* __restrict__ ef,
                                                float* __restrict__ out) {
    extern __shared__ float sm[];
    float* W2_2 = sm;               // 4096
    float* W3_2 = sm + 4096;        // 4096
    // per-warp region at 8192 + w*1024

    for (int i = threadIdx.x; i < 4096; i += 512) {
        W2_2[i] = W2[8192 + i];
        W3_2[i] = W3[8192 + i];
    }
    __syncthreads();

    const int w = threadIdx.x >> 5, l = threadIdx.x & 31;
    const int d0 = 2 * l, d1 = d0 + 1;
    float* wb = sm + 8192 + w * 1024;
    u64t* yb = (u64t*)wb;
    int* idxw = (int*)(wb + 512);
    float* ew = wb + 640;

    const float* Wb2 = W1 + 16768 + 128 * 64;
    const float e20 = Wb2[d0], e21 = Wb2[64 + d0], e22 = Wb2[128 + d0];
    const float e23 = Wb2[d1], e24 = Wb2[64 + d1], e25 = Wb2[128 + d1];
    const u64t bias2 = pack2(b2[128 + d0], b2[128 + d1]);
    const u64t bias3 = pack2(b3[128 + d0], b3[128 + d1]);

    const int stride = gridDim.x * 16;
    for (int g = blockIdx.x * 16 + w; g < BN / 4; g += stride) {
        const int base = g * 4;
        __syncwarp();
#pragma unroll
        for (int t = 0; t < 4; t++)
            idxw[t * 32 + l] = nidx[(size_t)(base + t) * 32 + l];
#pragma unroll
        for (int i = 0; i < 12; i++)
            ew[i * 32 + l] = ef[(size_t)base * 96 + i * 32 + l];
        __syncwarp();

        const size_t rowbase = (size_t)(base & ~(NPTS - 1)) * 64;
        const float* P2b = g_P2 + rowbase + d0;
        float ma[4], mb[4];
#pragma unroll
        for (int t = 0; t < 4; t++) { ma[t] = mb[t] = -3e38f; }
#pragma unroll
        for (int t = 0; t < 4; t++) {
#pragma unroll 8
            for (int k = 0; k < KNB; k++) {
                const int joff = idxw[t * 32 + k] * 64;
                float2 q = *(const float2*)(P2b + joff);
                float f0 = ew[t * 96 + 3 * k], f1 = ew[t * 96 + 3 * k + 1], f2 = ew[t * 96 + 3 * k + 2];
                float tt;
                tt = fmaf(f0, e20, fmaf(f1, e21, f2 * e22)); ma[t] = fmaxf(ma[t], q.x + tt);
                tt = fmaf(f0, e23, fmaf(f1, e24, f2 * e25)); mb[t] = fmaxf(mb[t], q.y + tt);
            }
        }

        __syncwarp();
#pragma unroll
        for (int t = 0; t < 4; t++) {
            float ya = lrelu(ma[t]), yc = lrelu(mb[t]);
            yb[t * 64 + d0] = pack2(ya, ya);
            yb[t * 64 + d1] = pack2(yc, yc);
        }
        __syncwarp();
        u64t acc[4] = {bias2, bias2, bias2, bias2};
        mm64b(yb, W2_2, acc, l);
        __syncwarp();
#pragma unroll
        for (int t = 0; t < 4; t++) {
            float2 v = unpack2(acc[t]);
            v.x = lrelu(v.x); v.y = lrelu(v.y);
            yb[t * 64 + d0] = pack2(v.x, v.x);
            yb[t * 64 + d1] = pack2(v.y, v.y);
        }
        __syncwarp();
        acc[0] = acc[1] = acc[2] = acc[3] = bias3;
        mm64b(yb, W3_2, acc, l);
#pragma unroll
        for (int t = 0; t < 4; t++) {
            float2 v = unpack2(acc[t]);
            float qa = tanhf(v.x), qb = tanhf(v.y);
            float2 zf = ((const float2*)g_z)[(size_t)(base + t) * 32 + l];
            float2 hv = ((const float2*)h)[(size_t)(base + t) * 32 + l];
            float2 o;
            o.x = hv.x + zf.x * (qa - hv.x);
            o.y = hv.y + zf.y * (qb - hv.y);
            ((float2*)out)[(size_t)(base + t) * 32 + l] = o;
        }
    }
}

// ---------------------------------------------------------------------------
extern "C" void kernel_launch(void* const* d_in, const int* in_sizes, int n_in,
                              void* d_out, int out_size) {
    const float* h  = (const float*)d_in[0];
    const float* x  = (const float*)d_in[1];
    // d_in[2] = c (unused by reference)
    const float* W1 = (const float*)d_in[3];
    const float* b1 = (const float*)d_in[4];
    const float* W2 = (const float*)d_in[5];
    const float* b2 = (const float*)d_in[6];
    const float* W3 = (const float*)d_in[7];
    const float* b3 = (const float*)d_in[8];
    const int* nidx = (const int*)d_in[9];
    const float* ef = (const float*)d_in[10];
    float* out = (float*)d_out;

    const int SMEM_PROJ = (20480 + 16 * 1024) * 4;   // 147456 B
    const int SMEM_ZR   = (20480 + 16 * 1024) * 4;   // 147456 B
    const int SMEM_OUT  = (8192  + 16 * 1024) * 4;   //  98304 B
    cudaFuncSetAttribute(k_proj, cudaFuncAttributeMaxDynamicSharedMemorySize, SMEM_PROJ);
    cudaFuncSetAttribute(k_zr,   cudaFuncAttributeMaxDynamicSharedMemorySize, SMEM_ZR);
    cudaFuncSetAttribute(k_out,  cudaFuncAttributeMaxDynamicSharedMemorySize, SMEM_OUT);

    k_proj<<<152, 512, SMEM_PROJ>>>(h, x, W1, b1);
    k_zr  <<<152, 512, SMEM_ZR>>>(h, W1, W2, b2, W3, b3, nidx, ef);
    k_out <<<256, 512, SMEM_OUT>>>(h, W1, W2, b2, W3, b3, nidx, ef, out);
}

// round 4
// speedup vs baseline: 1.3606x; 1.0350x over previous
#include <cuda_runtime.h>
#include <math.h>

#define BN      32768      // B*N
#define NPTS    8192       // N
#define NGROUPS 4096       // BN / 8
#define NWARPS  12
#define NTHR    384

typedef unsigned long long u64t;

// Scratch (device globals: no allocation allowed)
__device__ float g_P0[BN * 64];
__device__ float g_P1[BN * 64];
__device__ float g_Px2[BN * 64];
__device__ float g_P2[BN * 64];
__device__ float g_z[BN * 64];
__device__ unsigned int g_ctr[3];   // work-stealing counters (zero-init)

__device__ __forceinline__ u64t pack2(float lo, float hi) {
    u64t r; asm("mov.b64 %0, {%1, %2};" : "=l"(r) : "f"(lo), "f"(hi)); return r;
}
__device__ __forceinline__ float2 unpack2(u64t v) {
    float2 r; asm("mov.b64 {%0, %1}, %2;" : "=f"(r.x), "=f"(r.y) : "l"(v)); return r;
}
// Packed fp32x2 FMA (sm_100+; PTX-only, ptxas never auto-fuses)
__device__ __forceinline__ void ffma2(u64t &d, u64t a, u64t b) {
    asm("fma.rn.f32x2 %0, %1, %2, %0;" : "+l"(d) : "l"(a), "l"(b));
}

__device__ __forceinline__ float lrelu(float v) { return fmaxf(v, 0.1f * v); }
__device__ __forceinline__ float sigmoidf_(float v) { return 1.0f / (1.0f + __expf(-v)); }

// Fetch next work group (warp-cooperative)
__device__ __forceinline__ int next_group(unsigned int* ctr, int lane) {
    int g = 0;
    if (lane == 0) g = (int)atomicAdd(ctr, 1u);
    return __shfl_sync(0xffffffffu, g, 0);
}

// Batched 64x64 matmul tail, T=8 points. yb: [t][c] duplicated pairs (u64).
// Vectorized: channel-pair LDS.128 per point, weight pair loaded once.
__device__ __forceinline__ void mm64b8(const u64t* __restrict__ yb,
                                       const float* __restrict__ Wm,
                                       u64t* acc, int l) {
    const u64t* Wu = (const u64t*)Wm;
#pragma unroll 8
    for (int c2 = 0; c2 < 32; c2++) {
        const int c0 = 2 * c2;
        u64t w0 = Wu[c0 * 32 + l];
        u64t w1 = Wu[(c0 + 1) * 32 + l];
#pragma unroll
        for (int t = 0; t < 8; t++) {
            ulonglong2 y = *(const ulonglong2*)(yb + t * 64 + c0);
            ffma2(acc[t], y.x, w0);
            ffma2(acc[t], y.y, w1);
        }
    }
}

// ---------------------------------------------------------------------------
// Kernel 1: projections (T=8).
//   P0 = hx@W1[0][:128]+b1[0], P1 = hx@W1[1][:128]+b1[1], Px2 = x@W1[2][64:128]+b1[2]
// ---------------------------------------------------------------------------
__global__ __launch_bounds__(NTHR, 1) void k_proj(const float* __restrict__ h,
                                                  const float* __restrict__ x,
                                                  const float* __restrict__ W1,
                                                  const float* __restrict__ b1) {
    extern __shared__ float sm[];
    float* Wa0 = sm;              // 128*64
    float* Wa1 = sm + 8192;
    float* Wx2 = sm + 16384;      // 64*64

    for (int i = threadIdx.x; i < 8192; i += NTHR) {
        Wa0[i] = W1[i];
        Wa1[i] = W1[8384 + i];
    }
    for (int i = threadIdx.x; i < 4096; i += NTHR)
        Wx2[i] = W1[20864 + i];
    if (blockIdx.x == 0 && threadIdx.x == 0) g_ctr[2] = 0;  // reset for k_out
    __syncthreads();

    const int w = threadIdx.x >> 5, l = threadIdx.x & 31;
    const int d0 = 2 * l, d1 = d0 + 1;
    u64t* actd = (u64t*)(sm + 20480 + w * 2048);   // [t][c] 8*128 u64
    const u64t* Wa0u = (const u64t*)Wa0;
    const u64t* Wa1u = (const u64t*)Wa1;
    const u64t* Wx2u = (const u64t*)Wx2;

    const u64t bb0 = pack2(b1[d0], b1[d1]);
    const u64t bb1 = pack2(b1[64 + d0], b1[64 + d1]);
    const u64t bb2 = pack2(b1[128 + d0], b1[128 + d1]);

    for (;;) {
        const int g = next_group(&g_ctr[0], l);
        if (g >= NGROUPS) break;
        const int base = g * 8;

        __syncwarp();
#pragma unroll
        for (int t = 0; t < 8; t++) {
            float2 hv = ((const float2*)h)[(size_t)(base + t) * 32 + l];
            float2 xv = ((const float2*)x)[(size_t)(base + t) * 32 + l];
            ulonglong2 hd; hd.x = pack2(hv.x, hv.x); hd.y = pack2(hv.y, hv.y);
            ulonglong2 xd; xd.x = pack2(xv.x, xv.x); xd.y = pack2(xv.y, xv.y);
            *(ulonglong2*)(actd + t * 128 + d0) = hd;
            *(ulonglong2*)(actd + t * 128 + 64 + d0) = xd;
        }
        __syncwarp();

        u64t a0[8], a1[8], a2[8];
#pragma unroll
        for (int t = 0; t < 8; t++) { a0[t] = bb0; a1[t] = bb1; a2[t] = bb2; }

#pragma unroll 2
        for (int c2 = 0; c2 < 32; c2++) {
            const int c0 = 2 * c2;
            u64t wh0a = Wa0u[c0 * 32 + l],        wh0b = Wa0u[(c0 + 1) * 32 + l];
            u64t wx0a = Wa0u[(64 + c0) * 32 + l], wx0b = Wa0u[(65 + c0) * 32 + l];
            u64t wh1a = Wa1u[c0 * 32 + l],        wh1b = Wa1u[(c0 + 1) * 32 + l];
            u64t wx1a = Wa1u[(64 + c0) * 32 + l], wx1b = Wa1u[(65 + c0) * 32 + l];
            u64t wx2a = Wx2u[c0 * 32 + l],        wx2b = Wx2u[(c0 + 1) * 32 + l];
#pragma unroll
            for (int t = 0; t < 8; t++) {
                ulonglong2 yh = *(const ulonglong2*)(actd + t * 128 + c0);
                ulonglong2 yx = *(const ulonglong2*)(actd + t * 128 + 64 + c0);
                ffma2(a0[t], yh.x, wh0a); ffma2(a0[t], yh.y, wh0b);
                ffma2(a0[t], yx.x, wx0a); ffma2(a0[t], yx.y, wx0b);
                ffma2(a1[t], yh.x, wh1a); ffma2(a1[t], yh.y, wh1b);
                ffma2(a1[t], yx.x, wx1a); ffma2(a1[t], yx.y, wx1b);
                ffma2(a2[t], yx.x, wx2a); ffma2(a2[t], yx.y, wx2b);
            }
        }
#pragma unroll
        for (int t = 0; t < 8; t++) {
            ((float2*)g_P0)[(size_t)(base + t) * 32 + l] = unpack2(a0[t]);
            ((float2*)g_P1)[(size_t)(base + t) * 32 + l] = unpack2(a1[t]);
            ((float2*)g_Px2)[(size_t)(base + t) * 32 + l] = unpack2(a2[t]);
        }
    }
}

// ---------------------------------------------------------------------------
// Kernel 2: gather+pool conv0/1 (T=8, packed edge math), tails -> z, r -> rh -> P2
// ---------------------------------------------------------------------------
__global__ __launch_bounds__(NTHR, 1) void k_zr(const float* __restrict__ h,
                                                const float* __restrict__ W1,
                                                const float* __restrict__ W2,
                                                const float* __restrict__ b2,
                                                const float* __restrict__ W3,
                                                const float* __restrict__ b3,
                                                const int* __restrict__ nidx,
                                                const float* __restrict__ ef) {
    extern __shared__ float sm[];
    float* W2_0 = sm;
    float* W3_0 = sm + 4096;
    float* W2_1 = sm + 8192;
    float* W3_1 = sm + 12288;
    float* W1ch = sm + 16384;       // W1[2][0:64,:]

    for (int i = threadIdx.x; i < 4096; i += NTHR) {
        W2_0[i] = W2[i];        W3_0[i] = W3[i];
        W2_1[i] = W2[4096 + i]; W3_1[i] = W3[4096 + i];
        W1ch[i] = W1[16768 + i];
    }
    if (blockIdx.x == 0 && threadIdx.x == 0) g_ctr[0] = 0;  // reset for k_proj (next replay)
    __syncthreads();

    const int w = threadIdx.x >> 5, l = threadIdx.x & 31;
    const int d0 = 2 * l, d1 = d0 + 1;
    float* wbase = sm + 20480 + w * 2816;
    u64t* yb = (u64t*)wbase;                 // [t][c] 8*64 u64
    int*  idxs = (int*)(wbase + 1024);       // 8*32
    u64t* ewA = (u64t*)(wbase + 1280);       // (f0,f0) per (t,k)
    u64t* ewB = (u64t*)(wbase + 1792);
    u64t* ewC = (u64t*)(wbase + 2304);

    const float* Wb0 = W1 + 8192;
    const float* Wb1 = W1 + 16576;
    const u64t e0c0 = pack2(Wb0[d0], Wb0[d1]);
    const u64t e1c0 = pack2(Wb0[64 + d0], Wb0[64 + d1]);
    const u64t e2c0 = pack2(Wb0[128 + d0], Wb0[128 + d1]);
    const u64t e0c1 = pack2(Wb1[d0], Wb1[d1]);
    const u64t e1c1 = pack2(Wb1[64 + d0], Wb1[64 + d1]);
    const u64t e2c1 = pack2(Wb1[128 + d0], Wb1[128 + d1]);
    const u64t bias20 = pack2(b2[d0], b2[d1]),           bias30 = pack2(b3[d0], b3[d1]);
    const u64t bias21 = pack2(b2[64 + d0], b2[64 + d1]), bias31 = pack2(b3[64 + d0], b3[64 + d1]);

    for (;;) {
        const int g = next_group(&g_ctr[1], l);
        if (g >= NGROUPS) break;
        const int base = g * 8;

        __syncwarp();
#pragma unroll
        for (int t = 0; t < 8; t++)
            idxs[t * 32 + l] = nidx[(size_t)(base + t) * 32 + l];
#pragma unroll
        for (int t = 0; t < 8; t++) {
            const float* efp = ef + (size_t)(base + t) * 96 + 3 * l;
            float f0 = efp[0], f1 = efp[1], f2 = efp[2];
            ewA[t * 32 + l] = pack2(f0, f0);
            ewB[t * 32 + l] = pack2(f1, f1);
            ewC[t * 32 + l] = pack2(f2, f2);
        }
        __syncwarp();

        const size_t rowb = (size_t)(base & ~(NPTS - 1)) * 64;
        const char* P0b = (const char*)(g_P0 + rowb + d0);
        const char* P1b = (const char*)(g_P1 + rowb + d0);
        float m0a[8], m0b[8], m1a[8], m1b[8];
#pragma unroll
        for (int t = 0; t < 8; t++) {
            float a0m = -3e38f, b0m = -3e38f, a1m = -3e38f, b1m = -3e38f;
            const int* idxt = idxs + t * 32;
            const u64t* eA = ewA + t * 32;
            const u64t* eB = ewB + t * 32;
            const u64t* eC = ewC + t * 32;
#pragma unroll 8
            for (int k = 0; k < 32; k++) {
                const int joff = idxt[k] << 8;     // *64 floats *4B
                u64t q0 = *(const u64t*)(P0b + joff);
                u64t q1 = *(const u64t*)(P1b + joff);
                u64t f0 = eA[k], f1 = eB[k], f2 = eC[k];
                u64t s0 = q0; ffma2(s0, f0, e0c0); ffma2(s0, f1, e1c0); ffma2(s0, f2, e2c0);
                u64t s1 = q1; ffma2(s1, f0, e0c1); ffma2(s1, f1, e1c1); ffma2(s1, f2, e2c1);
                float2 v0 = unpack2(s0), v1 = unpack2(s1);
                a0m = fmaxf(a0m, v0.x); b0m = fmaxf(b0m, v0.y);
                a1m = fmaxf(a1m, v1.x); b1m = fmaxf(b1m, v1.y);
            }
            m0a[t] = a0m; m0b[t] = b0m; m1a[t] = a1m; m1b[t] = b1m;
        }

        u64t acc[8];
        // --- conv0 tail -> z ---
        __syncwarp();
#pragma unroll
        for (int t = 0; t < 8; t++) {
            float ya = lrelu(m0a[t]), yc = lrelu(m0b[t]);
            ulonglong2 v; v.x = pack2(ya, ya); v.y = pack2(yc, yc);
            *(ulonglong2*)(yb + t * 64 + d0) = v;
        }
        __syncwarp();
#pragma unroll
        for (int t = 0; t < 8; t++) acc[t] = bias20;
        mm64b8(yb, W2_0, acc, l);
        __syncwarp();
#pragma unroll
        for (int t = 0; t < 8; t++) {
            float2 v = unpack2(acc[t]);
            v.x = lrelu(v.x); v.y = lrelu(v.y);
            ulonglong2 u; u.x = pack2(v.x, v.x); u.y = pack2(v.y, v.y);
            *(ulonglong2*)(yb + t * 64 + d0) = u;
        }
        __syncwarp();
#pragma unroll
        for (int t = 0; t < 8; t++) acc[t] = bias30;
        mm64b8(yb, W3_0, acc, l);
#pragma unroll
        for (int t = 0; t < 8; t++) {
            float2 v = unpack2(acc[t]);
            float2 zf; zf.x = sigmoidf_(v.x); zf.y = sigmoidf_(v.y);
            ((float2*)g_z)[(size_t)(base + t) * 32 + l] = zf;
        }

        // --- conv1 tail -> r -> rh -> P2 ---
        __syncwarp();
#pragma unroll
        for (int t = 0; t < 8; t++) {
            float ya = lrelu(m1a[t]), yc = lrelu(m1b[t]);
            ulonglong2 v; v.x = pack2(ya, ya); v.y = pack2(yc, yc);
            *(ulonglong2*)(yb + t * 64 + d0) = v;
        }
        __syncwarp();
#pragma unroll
        for (int t = 0; t < 8; t++) acc[t] = bias21;
        mm64b8(yb, W2_1, acc, l);
        __syncwarp();
#pragma unroll
        for (int t = 0; t < 8; t++) {
            float2 v = unpack2(acc[t]);
            v.x = lrelu(v.x); v.y = lrelu(v.y);
            ulonglong2 u; u.x = pack2(v.x, v.x); u.y = pack2(v.y, v.y);
            *(ulonglong2*)(yb + t * 64 + d0) = u;
        }
        __syncwarp();
#pragma unroll
        for (int t = 0; t < 8; t++) acc[t] = bias31;
        mm64b8(yb, W3_1, acc, l);
        __syncwarp();
#pragma unroll
        for (int t = 0; t < 8; t++) {
            float2 v = unpack2(acc[t]);
            float2 hv = ((const float2*)h)[(size_t)(base + t) * 32 + l];
            float ra = sigmoidf_(v.x) * hv.x;
            float rb = sigmoidf_(v.y) * hv.y;
            ulonglong2 u; u.x = pack2(ra, ra); u.y = pack2(rb, rb);
            *(ulonglong2*)(yb + t * 64 + d0) = u;
        }
        __syncwarp();
#pragma unroll
        for (int t = 0; t < 8; t++) {
            float2 px = ((const float2*)g_Px2)[(size_t)(base + t) * 32 + l];
            acc[t] = pack2(px.x, px.y);
        }
        mm64b8(yb, W1ch, acc, l);
#pragma unroll
        for (int t = 0; t < 8; t++)
            ((float2*)g_P2)[(size_t)(base + t) * 32 + l] = unpack2(acc[t]);
    }
}

// ---------------------------------------------------------------------------
// Kernel 3: gather+pool conv2 (T=8), tail -> q, out = h + z*(q-h)
// ---------------------------------------------------------------------------
__global__ __launch_bounds__(NTHR, 1) void k_out(const float* __restrict__ h,
                                                 const float* __restrict__ W1,
                                                 const float* __restrict__ W2,
                                                 const float* __restrict__ b2,
                                                 const float* __restrict__ W3,
                                                 const float* __restrict__ b3,
                                                 const int* __restrict__ nidx,
                                                 const float* __restrict__ ef,
                                                 float* __restrict__ out) {
    extern __shared__ float sm[];
    float* W2_2 = sm;               // 4096
    float* W3_2 = sm + 4096;

    for (int i = threadIdx.x; i < 4096; i += NTHR) {
        W2_2[i] = W2[8192 + i];
        W3_2[i] = W3[8192 + i];
    }
    if (blockIdx.x == 0 && threadIdx.x == 0) g_ctr[1] = 0;  // reset for k_zr (next replay)
    __syncthreads();

    const int w = threadIdx.x >> 5, l = threadIdx.x & 31;
    const int d0 = 2 * l, d1 = d0 + 1;
    float* wbase = sm + 8192 + w * 2816;
    u64t* yb = (u64t*)wbase;
    int*  idxs = (int*)(wbase + 1024);
    u64t* ewA = (u64t*)(wbase + 1280);
    u64t* ewB = (u64t*)(wbase + 1792);
    u64t* ewC = (u64t*)(wbase + 2304);

    const float* Wb2 = W1 + 24960;
    const u64t e0c = pack2(Wb2[d0], Wb2[d1]);
    const u64t e1c = pack2(Wb2[64 + d0], Wb2[64 + d1]);
    const u64t e2c = pack2(Wb2[128 + d0], Wb2[128 + d1]);
    const u64t bias2 = pack2(b2[128 + d0], b2[128 + d1]);
    const u64t bias3 = pack2(b3[128 + d0], b3[128 + d1]);

    for (;;) {
        const int g = next_group(&g_ctr[2], l);
        if (g >= NGROUPS) break;
        const int base = g * 8;

        __syncwarp();
#pragma unroll
        for (int t = 0; t < 8; t++)
            idxs[t * 32 + l] = nidx[(size_t)(base + t) * 32 + l];
#pragma unroll
        for (int t = 0; t < 8; t++) {
            const float* efp = ef + (size_t)(base + t) * 96 + 3 * l;
            float f0 = efp[0], f1 = efp[1], f2 = efp[2];
            ewA[t * 32 + l] = pack2(f0, f0);
            ewB[t * 32 + l] = pack2(f1, f1);
            ewC[t * 32 + l] = pack2(f2, f2);
        }
        __syncwarp();

        const size_t rowb = (size_t)(base & ~(NPTS - 1)) * 64;
        const char* P2b = (const char*)(g_P2 + rowb + d0);
        float ma[8], mb[8];
#pragma unroll
        for (int t = 0; t < 8; t++) {
            float am = -3e38f, bm = -3e38f;
            const int* idxt = idxs + t * 32;
            const u64t* eA = ewA + t * 32;
            const u64t* eB = ewB + t * 32;
            const u64t* eC = ewC + t * 32;
#pragma unroll 8
            for (int k = 0; k < 32; k++) {
                const int joff = idxt[k] << 8;
                u64t q = *(const u64t*)(P2b + joff);
                u64t s = q;
                ffma2(s, eA[k], e0c); ffma2(s, eB[k], e1c); ffma2(s, eC[k], e2c);
                float2 v = unpack2(s);
                am = fmaxf(am, v.x); bm = fmaxf(bm, v.y);
            }
            ma[t] = am; mb[t] = bm;
        }

        u64t acc[8];
        __syncwarp();
#pragma unroll
        for (int t = 0; t < 8; t++) {
            float ya = lrelu(ma[t]), yc = lrelu(mb[t]);
            ulonglong2 v; v.x = pack2(ya, ya); v.y = pack2(yc, yc);
            *(ulonglong2*)(yb + t * 64 + d0) = v;
        }
        __syncwarp();
#pragma unroll
        for (int t = 0; t < 8; t++) acc[t] = bias2;
        mm64b8(yb, W2_2, acc, l);
        __syncwarp();
#pragma unroll
        for (int t = 0; t < 8; t++) {
            float2 v = unpack2(acc[t]);
            v.x = lrelu(v.x); v.y = lrelu(v.y);
            ulonglong2 u; u.x = pack2(v.x, v.x); u.y = pack2(v.y, v.y);
            *(ulonglong2*)(yb + t * 64 + d0) = u;
        }
        __syncwarp();
#pragma unroll
        for (int t = 0; t < 8; t++) acc[t] = bias3;
        mm64b8(yb, W3_2, acc, l);
#pragma unroll
        for (int t = 0; t < 8; t++) {
            float2 v = unpack2(acc[t]);
            float qa = tanhf(v.x), qb = tanhf(v.y);
            float2 zf = ((const float2*)g_z)[(size_t)(base + t) * 32 + l];
            float2 hv = ((const float2*)h)[(size_t)(base + t) * 32 + l];
            float2 o;
            o.x = hv.x + zf.x * (qa - hv.x);
            o.y = hv.y + zf.y * (qb - hv.y);
            ((float2*)out)[(size_t)(base + t) * 32 + l] = o;
        }
    }
}

// ---------------------------------------------------------------------------
extern "C" void kernel_launch(void* const* d_in, const int* in_sizes, int n_in,
                              void* d_out, int out_size) {
    const float* h  = (const float*)d_in[0];
    const float* x  = (const float*)d_in[1];
    // d_in[2] = c (unused by reference)
    const float* W1 = (const float*)d_in[3];
    const float* b1 = (const float*)d_in[4];
    const float* W2 = (const float*)d_in[5];
    const float* b2 = (const float*)d_in[6];
    const float* W3 = (const float*)d_in[7];
    const float* b3 = (const float*)d_in[8];
    const int* nidx = (const int*)d_in[9];
    const float* ef = (const float*)d_in[10];
    float* out = (float*)d_out;

    const int SMEM_PROJ = (20480 + NWARPS * 2048) * 4;   // 180224 B
    const int SMEM_ZR   = (20480 + NWARPS * 2816) * 4;   // 217088 B
    const int SMEM_OUT  = (8192  + NWARPS * 2816) * 4;   // 167936 B
    cudaFuncSetAttribute(k_proj, cudaFuncAttributeMaxDynamicSharedMemorySize, SMEM_PROJ);
    cudaFuncSetAttribute(k_zr,   cudaFuncAttributeMaxDynamicSharedMemorySize, SMEM_ZR);
    cudaFuncSetAttribute(k_out,  cudaFuncAttributeMaxDynamicSharedMemorySize, SMEM_OUT);

    k_proj<<<152, NTHR, SMEM_PROJ>>>(h, x, W1, b1);
    k_zr  <<<152, NTHR, SMEM_ZR>>>(h, W1, W2, b2, W3, b3, nidx, ef);
    k_out <<<152, NTHR, SMEM_OUT>>>(h, W1, W2, b2, W3, b3, nidx, ef, out);
}